// round 17
// baseline (speedup 1.0000x reference)
#include <cuda_runtime.h>
#include <cuda_fp16.h>
#include <math.h>
#include <stdint.h>

#define NB   64
#define TT   64
#define VV   25
#define DIMC 384
#define HH   6
#define HD   64
#define TV   1600                 // T*V
#define SL   39321600             // N*T*H*HD*V  (per-slot scratch size)
#define NSTRIDE 614400u           // T*H*HD*V    (per-n stride within a slot)
#define XPITCH 1664               // padded TV for cp.async (multiple of 128)

// Scratch: slots 0..4 = K, V, Q, EK, EQ, each [N,T,H,V,HD] fp32 (v-major inner)
__device__ float g_proj[5u * SL];
// Pre-converted GEMM operands (single fp16)
__device__ __half g_w16[1920 * 384];
__device__ __half g_x16[2u * NB * DIMC * XPITCH];
// Pre-converted, pre-swizzled per-head aux tiles (rpe 32x64, proj_w 64x64)
__device__ __align__(16) char g_r_sw[6 * 4096];
__device__ __align__(16) char g_pw_sw[6 * 8192];

// ---------------- helpers ----------------
__device__ __forceinline__ uint32_t smem_u32(const void* p) {
    uint32_t a;
    asm("{ .reg .u64 t; cvta.to.shared.u64 t, %1; cvt.u32.u64 %0, t; }"
        : "=r"(a) : "l"(p));
    return a;
}
__device__ __forceinline__ uint2 cvt4h(float4 v) {
    __half2 h0 = __floats2half2_rn(v.x, v.y);
    __half2 h1 = __floats2half2_rn(v.z, v.w);
    return make_uint2(*(uint32_t*)&h0, *(uint32_t*)&h1);
}
__device__ __forceinline__ void ldsm4(uint32_t addr, uint32_t* r) {
    asm volatile("ldmatrix.sync.aligned.m8n8.x4.shared.b16 {%0,%1,%2,%3}, [%4];"
                 : "=r"(r[0]), "=r"(r[1]), "=r"(r[2]), "=r"(r[3]) : "r"(addr));
}
__device__ __forceinline__ void ldsm4t(uint32_t addr, uint32_t* r) {
    asm volatile("ldmatrix.sync.aligned.m8n8.x4.trans.shared.b16 {%0,%1,%2,%3}, [%4];"
                 : "=r"(r[0]), "=r"(r[1]), "=r"(r[2]), "=r"(r[3]) : "r"(addr));
}
__device__ __forceinline__ void mma_f16(float* c, const uint32_t* a, const uint32_t* b) {
    asm volatile("mma.sync.aligned.m16n8k16.row.col.f32.f16.f16.f32 "
                 "{%0,%1,%2,%3}, {%4,%5,%6,%7}, {%8,%9}, {%0,%1,%2,%3};"
                 : "+f"(c[0]), "+f"(c[1]), "+f"(c[2]), "+f"(c[3])
                 : "r"(a[0]), "r"(a[1]), "r"(a[2]), "r"(a[3]), "r"(b[0]), "r"(b[1]));
}
__device__ __forceinline__ void cp16(uint32_t dst, const void* src) {
    asm volatile("cp.async.cg.shared.global [%0], [%1], 16;" :: "r"(dst), "l"(src));
}
__device__ __forceinline__ void cp_commit() {
    asm volatile("cp.async.commit_group;" ::: "memory");
}
template <int N>
__device__ __forceinline__ void cp_wait() {
    asm volatile("cp.async.wait_group %0;" :: "n"(N) : "memory");
}
// swizzled byte offset within a 128B-row tile, fp16 col c
__device__ __forceinline__ uint32_t swz_off(int row, int c) {
    return (uint32_t)(row * 128 + (((c >> 3) ^ (row & 7)) * 16) + (c & 7) * 2);
}

// =====================================================================
// Pre-convert kernels (fp32 -> fp16)
// =====================================================================
__global__ __launch_bounds__(256) void presplit_w(
    const float* __restrict__ kv_w, const float* __restrict__ q_w,
    const float* __restrict__ e_kv_w, const float* __restrict__ e_q_w)
{
    int id = blockIdx.x * 256 + threadIdx.x;
    if (id >= 1920 * 384 / 4) return;
    int idx4 = id * 4;
    int r = idx4 / 384, c = idx4 % 384;
    const float* src;
    if      (r < 768)  src = kv_w   + (size_t)r * 384 + c;
    else if (r < 1152) src = q_w    + (size_t)(r - 768) * 384 + c;
    else if (r < 1536) src = e_kv_w + (size_t)(r - 1152) * 384 + c;
    else               src = e_q_w  + (size_t)(r - 1536) * 384 + c;
    *(uint2*)&g_w16[idx4] = cvt4h(*(const float4*)src);
}

__global__ __launch_bounds__(256) void presplit_x(
    const float* __restrict__ x, const float* __restrict__ e)
{
    const int k = blockIdx.x, n = blockIdx.y, path = blockIdx.z;
    const float* src = (path ? e : x) + ((size_t)n * DIMC + k) * TV;
    size_t dst = ((size_t)(path * NB + n) * DIMC + k) * XPITCH;
    for (int l4 = threadIdx.x; l4 < XPITCH / 4; l4 += 256) {
        int f = l4 * 4;
        float4 v = (f < TV) ? *(const float4*)(src + f) : make_float4(0.f, 0.f, 0.f, 0.f);
        *(uint2*)&g_x16[dst + f] = cvt4h(v);
    }
}

// rpe (per-head 32x64, zero-padded) + proj_w (per-head 64x64) -> swizzled fp16
__global__ __launch_bounds__(256) void presplit_aux(
    const float* __restrict__ rpe, const float* __restrict__ proj_w, int nh)
{
    const int h = blockIdx.x;
    for (int idx = threadIdx.x; idx < 2048; idx += 256) {
        int row = idx >> 6, c = idx & 63;
        float val = (row < nh) ? rpe[(size_t)row * DIMC + h * 64 + c] : 0.f;
        *(__half*)(g_r_sw + h * 4096 + swz_off(row, c)) = __float2half(val);
    }
    for (int idx = threadIdx.x; idx < 4096; idx += 256) {
        int row = idx >> 6, c = idx & 63;
        float val = proj_w[((size_t)h * 64 + row) * 64 + c];
        *(__half*)(g_pw_sw + h * 8192 + swz_off(row, c)) = __float2half(val);
    }
}

// =====================================================================
// Projection GEMM via mma.sync fp16 (single MMA per tile). Unchanged.
// =====================================================================
#define A_PITCH 80
#define B_PITCH 272
#define A_BYTES (128 * A_PITCH)                  // 10240
#define B_BYTES (32 * B_PITCH)                   // 8704
#define STAGE_BYTES (A_BYTES + B_BYTES)          // 18944
#define DYN_BYTES 67584

__global__ __launch_bounds__(256, 2)
void proj_mma()
{
    const int nt  = blockIdx.x;
    const int mt  = blockIdx.y;
    const int n   = blockIdx.z;
    const int tid = threadIdx.x;
    const int lane = tid & 31;
    const int w    = tid >> 5;
    const int wm   = w & 3;
    const int wn   = w >> 2;

    extern __shared__ char smem[];
    const uint32_t smem_b = smem_u32(smem);

    const int path = (mt >= 9);
    const int o_origin = (mt < 12) ? ((mt < 9) ? mt * 128 : (mt - 9) * 128)
                                   : (384 + (mt - 12) * 128);
    const int wrow0 = mt * 128;
    const int p0 = nt * 128;

    const __half* X16 = g_x16 + ((size_t)(path * NB + n) * DIMC) * XPITCH;

    const int a_row0 = (tid * 2) >> 2;
    const int a_s0   = (tid * 2) & 3;
    const int b_row0 = (tid * 2) >> 4;
    const int b_s0   = (tid * 2) & 15;

    const uint32_t aoff = (uint32_t)((wm * 32 + (lane & 15)) * A_PITCH + (lane >> 4) * 16);
    const uint32_t boff = (uint32_t)((lane & 15) * B_PITCH + (wn * 64 + (lane >> 4) * 8) * 2);

    float acc[16][4];
#pragma unroll
    for (int i = 0; i < 16; i++)
#pragma unroll
        for (int j = 0; j < 4; j++) acc[i][j] = 0.f;

    auto issue = [&](int c) {
        const int k0 = c * 32;
        const uint32_t st = smem_b + (uint32_t)((c % 3) * STAGE_BYTES);
#pragma unroll
        for (int i = 0; i < 2; i++) {
            int as = (a_s0 + i) & 3;
            size_t asrc = (size_t)(wrow0 + a_row0) * 384 + k0 + as * 8;
            cp16(st + (uint32_t)(a_row0 * A_PITCH + as * 16), g_w16 + asrc);
            int bs = (b_s0 + i) & 15;
            size_t bsrc = (size_t)(k0 + b_row0) * XPITCH + p0 + bs * 8;
            cp16(st + (uint32_t)(A_BYTES + b_row0 * B_PITCH + bs * 16), X16 + bsrc);
        }
        cp_commit();
    };

    issue(0);
    issue(1);

    for (int c = 0; c < 12; ++c) {
        if (c < 11) cp_wait<1>(); else cp_wait<0>();
        __syncthreads();
        if (c < 10) issue(c + 2);

        const uint32_t stage = smem_b + (uint32_t)((c % 3) * STAGE_BYTES);
        const uint32_t aA = stage + aoff;
        const uint32_t bB = stage + A_BYTES + boff;
#pragma unroll
        for (int s = 0; s < 2; s++) {
            uint32_t Ah[2][4];
#pragma unroll
            for (int m = 0; m < 2; m++)
                ldsm4(aA + m * 16 * A_PITCH + s * 32, Ah[m]);
            uint32_t Bh[4][4];
#pragma unroll
            for (int g = 0; g < 4; g++)
                ldsm4t(bB + s * 16 * B_PITCH + g * 32, Bh[g]);
#pragma unroll
            for (int m = 0; m < 2; m++)
#pragma unroll
                for (int g = 0; g < 4; g++)
#pragma unroll
                    for (int half = 0; half < 2; half++)
                        mma_f16(acc[m * 8 + g * 2 + half], Ah[m], &Bh[g][half * 2]);
        }
        __syncthreads();
    }

    float* stg = (float*)smem;
    const int g   = lane >> 2;
    const int tig = lane & 3;
#pragma unroll
    for (int m = 0; m < 2; m++) {
#pragma unroll
        for (int ntile = 0; ntile < 8; ntile++) {
#pragma unroll
            for (int j = 0; j < 4; j++) {
                int o  = wm * 32 + m * 16 + g + (j >> 1) * 8;
                int pl = wn * 64 + ntile * 8 + tig * 2 + (j & 1);
                stg[pl * 132 + o] = acc[m * 8 + ntile][j];
            }
        }
    }
    __syncthreads();

    const int slot = (o_origin / 384) + (path ? 3 : 0);
    const int hh0  = (o_origin % 384) >> 6;
    const size_t obase = (size_t)slot * SL + (size_t)n * NSTRIDE;
#pragma unroll
    for (int i = 0; i < 16; i++) {
        int f  = tid + 256 * i;
        int pl = f >> 5;
        int o  = (f & 31) * 4;
        uint32_t p = (uint32_t)(p0 + pl);
        if (p < TV) {
            uint32_t t = (p * 5243u) >> 17;
            uint32_t v = p - t * 25u;
            uint32_t hh = (uint32_t)(hh0 + (o >> 6));
            uint32_t d  = (uint32_t)(o & 63);
            float* sp = &stg[pl * 132 + o];
            float4 val = make_float4(sp[0], sp[1], sp[2], sp[3]);
            *(float4*)&g_proj[obase + t * 9600u + hh * 1600u + v * 64u + d] = val;
        }
    }
}

// =====================================================================
// Kernel B: dual-t attention. 256 threads; sub-block (tid>>7) owns one t.
// Shared across subs: R tile (4KB), PW tile (8KB), hops.
// Private per sub: 16KB tile region (Q,EQ,KE,EK; reused as XO in ph4-5),
//                  2112-float score buffer (OS/OD/OQR).
// Dynamic smem map (bytes):
//   [0,32768)       priv[2] (16384 each)
//   [32768,36864)   R (shared)
//   [36864,45056)   PW (shared)
//   [45056,61952)   smf[2] (8448 each: OS 0, OD 700, OQR 1400)
//   [61952,62592)   hops
// =====================================================================
#define ATTN_DYN 62592
#define R_SH   32768
#define PW_SH  36864
#define SMF_B  45056
#define HOPS_B 61952
#define Q16_O  0
#define EQ16_O 4096
#define KE16_O 8192
#define EK16_O 12288
#define XO16_O 0
#define OS_F   0
#define OD_F   700
#define OQR_F  1400

__global__ __launch_bounds__(256) void attn_kernel(
    const float* __restrict__ outer,
    const float* __restrict__ alpha_p, const float* __restrict__ beta_p,
    const float* __restrict__ proj_b,
    const int* __restrict__ hops, int nh,
    float* __restrict__ xo_out, float* __restrict__ eo_out)
{
    const int h = blockIdx.x, n = blockIdx.z;
    const int tid = threadIdx.x;
    const int sub = tid >> 7;
    const int st  = tid & 127;
    const int t   = blockIdx.y * 2 + sub;
    const int lane = tid & 31;
    const int w = st >> 5;          // warp within sub, 0..3

    extern __shared__ __align__(16) char smd[];
    const uint32_t smd_u = smem_u32(smd);
    char* priv = smd + sub * 16384;
    const uint32_t priv_u = smd_u + (uint32_t)(sub * 16384);
    float* smf = (float*)(smd + SMF_B + sub * 8448);
    unsigned char* shops = (unsigned char*)(smd + HOPS_B);

    const size_t base = (((size_t)n * TT + t) * HH + h) * (size_t)(HD * VV);

    // ---- phase 0: pads + load/convert private tiles; shared R/PW/hops ----
    for (int z = st; z < 224; z += 128) {
        int r = z >> 3, c = z & 7;
        int mtx = r / 7, row = 25 + (r % 7);
        *(float4*)(priv + mtx * 4096 + row * 128 + c * 16) =
            make_float4(0.f, 0.f, 0.f, 0.f);
    }
    for (int l4 = st; l4 < 400; l4 += 128) {
        int f = l4 * 4;
        int v = f >> 6, d = f & 63;
        float4 k4  = *(const float4*)&g_proj[0 * (size_t)SL + base + f];
        float4 q4  = *(const float4*)&g_proj[2 * (size_t)SL + base + f];
        float4 ek4 = *(const float4*)&g_proj[3 * (size_t)SL + base + f];
        float4 eq4 = *(const float4*)&g_proj[4 * (size_t)SL + base + f];
        float4 ke4 = make_float4(k4.x + ek4.x, k4.y + ek4.y, k4.z + ek4.z, k4.w + ek4.w);
        uint32_t off = swz_off(v, d);
        *(uint2*)(priv + Q16_O  + off) = cvt4h(q4);
        *(uint2*)(priv + EQ16_O + off) = cvt4h(eq4);
        *(uint2*)(priv + KE16_O + off) = cvt4h(ke4);
        *(uint2*)(priv + EK16_O + off) = cvt4h(ek4);
    }
    if (tid < 256) {
        int i16 = tid;
        if (i16 < 256)
            *(uint4*)(smd + R_SH + i16 * 16) = *(const uint4*)(g_r_sw + h * 4096 + i16 * 16);
    }
    for (int i16 = tid; i16 < 512; i16 += 256)
        *(uint4*)(smd + PW_SH + i16 * 16) = *(const uint4*)(g_pw_sw + h * 8192 + i16 * 16);
    for (int l = tid; l < 625; l += 256) shops[l] = (unsigned char)hops[l];
    __syncthreads();

    // ---- phase 2: three GEMMs via mma (S1=Q.KE', G2=EQ.EK', QR=Q.R') ----
    {
        const int mt = w & 1;
        const int nb = (w >> 1) * 16;
        const int arow = mt * 16 + (lane & 15);
        const int brow = nb + (lane & 15);
        float accS[2][4], accD[2][4], accR[2][4];
#pragma unroll
        for (int i = 0; i < 2; i++)
#pragma unroll
            for (int j = 0; j < 4; j++) { accS[i][j] = 0.f; accD[i][j] = 0.f; accR[i][j] = 0.f; }

#pragma unroll
        for (int s = 0; s < 4; s++) {
            uint32_t abyte = (uint32_t)(arow * 128 + (((s * 2 + (lane >> 4)) ^ (arow & 7)) * 16));
            uint32_t bbyte = (uint32_t)(brow * 128 + (((s * 2 + (lane >> 4)) ^ (brow & 7)) * 16));
            uint32_t q[4], eq[4], ke[4], ek[4], r[4];
            ldsm4(priv_u + Q16_O  + abyte, q);
            ldsm4(priv_u + EQ16_O + abyte, eq);
            ldsm4(priv_u + KE16_O + bbyte, ke);
            ldsm4(priv_u + EK16_O + bbyte, ek);
            ldsm4(smd_u + R_SH + bbyte, r);
#pragma unroll
            for (int ns = 0; ns < 2; ns++) {
                uint32_t bKE[2] = {ke[ns], ke[ns + 2]};
                uint32_t bEK[2] = {ek[ns], ek[ns + 2]};
                uint32_t bR[2]  = {r[ns],  r[ns + 2]};
                mma_f16(accS[ns], q, bKE);
                mma_f16(accD[ns], eq, bEK);
                mma_f16(accR[ns], q, bR);
            }
        }
#pragma unroll
        for (int ns = 0; ns < 2; ns++) {
#pragma unroll
            for (int j = 0; j < 4; j++) {
                int row = mt * 16 + (lane >> 2) + (j >> 1) * 8;
                int col = nb + ns * 8 + (lane & 3) * 2 + (j & 1);
                if (row < 25 && col < nh)
                    smf[OQR_F + row * 28 + col] = accR[ns][j];
            }
        }
        __syncthreads();
#pragma unroll
        for (int ns = 0; ns < 2; ns++) {
#pragma unroll
            for (int j = 0; j < 4; j++) {
                int row = mt * 16 + (lane >> 2) + (j >> 1) * 8;
                int col = nb + ns * 8 + (lane & 3) * 2 + (j & 1);
                if (row < 25 && col < 25) {
                    float g2 = accD[ns][j];
                    float b = smf[OQR_F + row * 28 + shops[row * 25 + col]];
                    smf[OS_F + row * 28 + col] = accS[ns][j] + g2 + b;
                    smf[OD_F + row * 28 + col] = g2;
                }
            }
        }
    }
    __syncthreads();

    const float alpha = __ldg(alpha_p);
    const float beta  = __ldg(beta_p);
    const float scale = 0.125f;

    // ---- phase 3: softmax (50 rows per sub), fold alpha/outer/beta ----
    if (st < 50) {
        int i = st % 25;
        float* row = &smf[(st < 25 ? OS_F : OD_F) + i * 28];
        float m = -1e30f;
#pragma unroll
        for (int j = 0; j < 25; j++) m = fmaxf(m, row[j]);
        float ebuf[25];
        float s = 0.f;
#pragma unroll
        for (int j = 0; j < 25; j++) { float v = expf((row[j] - m) * scale); ebuf[j] = v; s += v; }
        float inv = 1.f / s;
        if (st < 25) {
            const float* orow = outer + (size_t)h * 625 + i * 25;
#pragma unroll
            for (int j = 0; j < 25; j++)
                row[j] = alpha * (ebuf[j] * inv) + __ldg(orow + j);
        } else {
#pragma unroll
            for (int j = 0; j < 25; j++)
                row[j] = beta * (ebuf[j] * inv);
        }
    }
    __syncthreads();

    // ---- phase 4: AV (V from gmem); XO -> fp16 private smem ----
    for (int z = st; z < 56; z += 128) {
        int r = 25 + (z >> 3), c = z & 7;
        *(float4*)(priv + XO16_O + r * 128 + c * 16) = make_float4(0.f, 0.f, 0.f, 0.f);
    }
    if (st < 80) {
        int ig = st / 16;
        int dg = st % 16;
        float aX[5][4], aE[5][4];
#pragma unroll
        for (int ii = 0; ii < 5; ii++)
#pragma unroll
            for (int dd = 0; dd < 4; dd++) { aX[ii][dd] = 0.f; aE[ii][dd] = 0.f; }
#pragma unroll
        for (int j = 0; j < 25; j++) {
            float4 v4 = __ldg((const float4*)&g_proj[1 * (size_t)SL + base + j * 64 + dg * 4]);
#pragma unroll
            for (int ii = 0; ii < 5; ii++) {
                float a  = smf[OS_F + (ig * 5 + ii) * 28 + j];
                float dc = smf[OD_F + (ig * 5 + ii) * 28 + j];
                aX[ii][0] += a * v4.x;  aX[ii][1] += a * v4.y;
                aX[ii][2] += a * v4.z;  aX[ii][3] += a * v4.w;
                aE[ii][0] += dc * v4.x; aE[ii][1] += dc * v4.y;
                aE[ii][2] += dc * v4.z; aE[ii][3] += dc * v4.w;
            }
        }
        const int d0 = dg * 4;
#pragma unroll
        for (int ii = 0; ii < 5; ii++) {
            int i = ig * 5 + ii;
#pragma unroll
            for (int dd = 0; dd < 4; dd++)
                eo_out[(((size_t)n * DIMC + h * HD + d0 + dd) * TT + t) * VV + i] = aE[ii][dd];
            float4 xv = make_float4(aX[ii][0], aX[ii][1], aX[ii][2], aX[ii][3]);
            *(uint2*)(priv + XO16_O + swz_off(i, d0)) = cvt4h(xv);
        }
    }
    __syncthreads();

    // ---- phase 5: grouped projection via mma: OUT(25x64) = XO(25x64).W'(64x64) ----
    {
        const int mt = w & 1;
        const int ng = w >> 1;
        const int arow = mt * 16 + (lane & 15);
        float accP[2][2][4];
#pragma unroll
        for (int a = 0; a < 2; a++)
#pragma unroll
            for (int b = 0; b < 2; b++)
#pragma unroll
                for (int j = 0; j < 4; j++) accP[a][b][j] = 0.f;

#pragma unroll
        for (int s = 0; s < 4; s++) {
            uint32_t abyte = (uint32_t)(arow * 128 + (((s * 2 + (lane >> 4)) ^ (arow & 7)) * 16));
            uint32_t xh[4];
            ldsm4(priv_u + XO16_O + abyte, xh);
#pragma unroll
            for (int nt2 = 0; nt2 < 2; nt2++) {
                int brow = (ng * 2 + nt2) * 16 + (lane & 15);
                uint32_t bbyte = (uint32_t)(brow * 128 + (((s * 2 + (lane >> 4)) ^ (brow & 7)) * 16));
                uint32_t wh[4];
                ldsm4(smd_u + PW_SH + bbyte, wh);
#pragma unroll
                for (int ns = 0; ns < 2; ns++) {
                    uint32_t bh[2] = {wh[ns], wh[ns + 2]};
                    mma_f16(accP[nt2][ns], xh, bh);
                }
            }
        }
#pragma unroll
        for (int nt2 = 0; nt2 < 2; nt2++) {
#pragma unroll
            for (int ns = 0; ns < 2; ns++) {
#pragma unroll
                for (int j = 0; j < 4; j++) {
                    int row = mt * 16 + (lane >> 2) + (j >> 1) * 8;
                    int col = (ng * 2 + nt2) * 16 + ns * 8 + (lane & 3) * 2 + (j & 1);
                    if (row < 25) {
                        float b = __ldg(proj_b + h * HD + col);
                        xo_out[(((size_t)n * DIMC + h * HD + col) * TT + t) * VV + row] =
                            accP[nt2][ns][j] + b;
                    }
                }
            }
        }
    }
}

extern "C" void kernel_launch(void* const* d_in, const int* in_sizes, int n_in,
                              void* d_out, int out_size)
{
    const float* x      = (const float*)d_in[0];
    const float* e      = (const float*)d_in[1];
    const float* kv_w   = (const float*)d_in[2];
    const float* q_w    = (const float*)d_in[3];
    const float* e_kv_w = (const float*)d_in[4];
    const float* e_q_w  = (const float*)d_in[5];
    const float* rpe    = (const float*)d_in[6];
    const float* outerp = (const float*)d_in[7];
    const float* alpha  = (const float*)d_in[8];
    const float* beta   = (const float*)d_in[9];
    const float* proj_w = (const float*)d_in[10];
    const float* proj_b = (const float*)d_in[11];
    const int*   hops   = (const int*)d_in[12];

    int nh = in_sizes[6] / DIMC;

    float* xo = (float*)d_out;
    float* eo = xo + (size_t)NB * DIMC * TT * VV;

    presplit_w<<<(1920 * 384 / 4 + 255) / 256, 256>>>(kv_w, q_w, e_kv_w, e_q_w);
    presplit_x<<<dim3(DIMC, NB, 2), 256>>>(x, e);
    presplit_aux<<<6, 256>>>(rpe, proj_w, nh);

    cudaFuncSetAttribute(proj_mma, cudaFuncAttributeMaxDynamicSharedMemorySize, DYN_BYTES);
    proj_mma<<<dim3(13, 15, NB), 256, DYN_BYTES>>>();
    cudaFuncSetAttribute(attn_kernel, cudaFuncAttributeMaxDynamicSharedMemorySize, ATTN_DYN);
    attn_kernel<<<dim3(HH, TT / 2, NB), 256, ATTN_DYN>>>(outerp, alpha, beta,
                                                         proj_b, hops, nh, xo, eo);
}